// round 8
// baseline (speedup 1.0000x reference)
#include <cuda_runtime.h>
#include <cstdint>

// Problem constants
#define BB   128   // batch
#define INW  256   // input width
#define HH   1024  // hidden
#define NP   512   // pairs per A layer
#define LP   128   // number of (A,B) layer pairs (L=256 layers total)
#define NT   128   // k2 threads (8 channels per thread)
#define FULLMASK 0xffffffffu

// Transposed trig tables: [layer][j][thread], lane stride 16B (coalesced).
// A: j=0..3 -> MZI pair 4t+j (channels 8t+2j, 8t+2j+1)
// B: j=0..3 -> MZI pair 4t+j (channels 8t+2j+1, 8t+2j+2); pair 511 = identity
// Padded +2 layers so depth-2 prefetch never faults.
__device__ float4 g_tA[LP + 2][4][NT];
__device__ float4 g_tB[LP + 2][4][NT];
__device__ float  g_pR[4][BB * HH];         // GEMM partials per K-chunk
__device__ float  g_pI[4][BB * HH];

// ---------------------------------------------------------------------------
// Kernel 1: blocks [0,128) = complex GEMM (K-split x4, N-tiles of 32)
//           blocks [128,256) = trig table build (one block per layer pair)
// ---------------------------------------------------------------------------
__global__ __launch_bounds__(256) void k1(
    const float* __restrict__ inR, const float* __restrict__ inI,
    const float* __restrict__ wR,  const float* __restrict__ wI,
    const float* __restrict__ A0,  const float* __restrict__ A1,
    const float* __restrict__ B0,  const float* __restrict__ B1)
{
    const int bid = blockIdx.x, tid = threadIdx.x;

    if (bid >= 128) {
        const int k = bid - 128;
        for (int idx = tid; idx < NP; idx += 256) {
            float c0, s0, c1, s1;
            sincosf(A0[k * NP + idx], &s0, &c0);
            sincosf(A1[k * NP + idx], &s1, &c1);
            g_tA[k][idx & 3][idx >> 2] = make_float4(c0, s0, c1, s1);
        }
        for (int idx = tid; idx < NP; idx += 256) {
            float ang0 = (idx < NP - 1) ? B0[k * (NP - 1) + idx] : 0.f;
            float ang1 = (idx < NP - 1) ? B1[k * (NP - 1) + idx] : 0.f;
            float c0, s0, c1, s1;
            sincosf(ang0, &s0, &c0);
            sincosf(ang1, &s1, &c1);
            g_tB[k][idx & 3][idx >> 2] = make_float4(c0, s0, c1, s1);
        }
        return;
    }

    // ---- complex GEMM: tile M=128, N=32, K-chunk=64 ----
    const int kc = bid >> 5, nt = bid & 31;
    const int k0 = kc * 64, n0 = nt * 32;

    __shared__ float sXR[32][132], sXI[32][132];
    __shared__ float sWR[32][33],  sWI[32][33];

    float accR[8][2], accI[8][2];
    #pragma unroll
    for (int r = 0; r < 8; r++)
        #pragma unroll
        for (int c = 0; c < 2; c++) { accR[r][c] = 0.f; accI[r][c] = 0.f; }

    const int mi = tid >> 4, ni = tid & 15;
    const int lm = tid & 127, kh = (tid >> 7) * 16;
    const int wn = tid >> 3,  wk = (tid & 7) * 4;

    for (int ks = 0; ks < 64; ks += 32) {
        __syncthreads();
        #pragma unroll
        for (int j = 0; j < 4; j++) {
            const int kk = kh + j * 4;
            float4 vR = *(const float4*)(inR + lm * INW + k0 + ks + kk);
            float4 vI = *(const float4*)(inI + lm * INW + k0 + ks + kk);
            sXR[kk+0][lm] = vR.x; sXR[kk+1][lm] = vR.y;
            sXR[kk+2][lm] = vR.z; sXR[kk+3][lm] = vR.w;
            sXI[kk+0][lm] = vI.x; sXI[kk+1][lm] = vI.y;
            sXI[kk+2][lm] = vI.z; sXI[kk+3][lm] = vI.w;
        }
        {
            float4 vR = *(const float4*)(wR + (n0 + wn) * INW + k0 + ks + wk);
            float4 vI = *(const float4*)(wI + (n0 + wn) * INW + k0 + ks + wk);
            sWR[wk+0][wn] = vR.x; sWR[wk+1][wn] = vR.y;
            sWR[wk+2][wn] = vR.z; sWR[wk+3][wn] = vR.w;
            sWI[wk+0][wn] = vI.x; sWI[wk+1][wn] = vI.y;
            sWI[wk+2][wn] = vI.z; sWI[wk+3][wn] = vI.w;
        }
        __syncthreads();

        #pragma unroll 8
        for (int kk = 0; kk < 32; kk++) {
            float aRv[8], aIv[8], bRv[2], bIv[2];
            *(float4*)&aRv[0] = *(const float4*)&sXR[kk][mi * 8];
            *(float4*)&aRv[4] = *(const float4*)&sXR[kk][mi * 8 + 4];
            *(float4*)&aIv[0] = *(const float4*)&sXI[kk][mi * 8];
            *(float4*)&aIv[4] = *(const float4*)&sXI[kk][mi * 8 + 4];
            bRv[0] = sWR[kk][ni*2]; bRv[1] = sWR[kk][ni*2+1];
            bIv[0] = sWI[kk][ni*2]; bIv[1] = sWI[kk][ni*2+1];
            #pragma unroll
            for (int r = 0; r < 8; r++)
                #pragma unroll
                for (int c = 0; c < 2; c++) {
                    accR[r][c] += aRv[r]*bRv[c] - aIv[r]*bIv[c];
                    accI[r][c] += aRv[r]*bIv[c] + aIv[r]*bRv[c];
                }
        }
    }

    #pragma unroll
    for (int r = 0; r < 8; r++) {
        const int m = mi * 8 + r;
        #pragma unroll
        for (int c = 0; c < 2; c++) {
            g_pR[kc][m * HH + n0 + ni*2 + c] = accR[r][c];
            g_pI[kc][m * HH + n0 + ni*2 + c] = accI[r][c];
        }
    }
}

// ---------------------------------------------------------------------------
// helpers
// ---------------------------------------------------------------------------
__device__ __forceinline__ float4 ldg_v4_pinned(const float4* p) {
    float4 v;
    asm volatile("ld.global.nc.v4.f32 {%0,%1,%2,%3}, [%4];"
                 : "=f"(v.x), "=f"(v.y), "=f"(v.z), "=f"(v.w) : "l"(p));
    return v;
}

__device__ __forceinline__ void pub_pred(uint32_t addr, int pred,
                                         float x, float y, float z) {
    asm volatile("{\n\t"
                 ".reg .pred p;\n\t"
                 "setp.ne.s32 p, %0, 0;\n\t"
                 "@p st.shared.v4.f32 [%1], {%2,%3,%4,%2};\n\t"
                 "}"
                 :: "r"(pred), "r"(addr), "f"(x), "f"(y), "f"(z)
                 : "memory");
}

__device__ __forceinline__ float4 lds4(uint32_t addr) {
    float4 v;
    asm volatile("ld.shared.v4.f32 {%0,%1,%2,%3}, [%4];"
                 : "=f"(v.x), "=f"(v.y), "=f"(v.z), "=f"(v.w) : "r"(addr)
                 : "memory");
    return v;
}

// ---------------------------------------------------------------------------
// Kernel 2: Clements mesh — 128 threads, 8 channels/thread.
// 4 A-MZIs + 3 mid-B MZIs thread-local (high ILP); 1 edge MZI via shfl;
// 3 warp boundaries via smem slots; ONE __syncthreads per layer pair.
// ---------------------------------------------------------------------------
__global__ __launch_bounds__(NT, 1) void k2(
    const float* __restrict__ stR, const float* __restrict__ stI,
    const float* __restrict__ bR,  const float* __restrict__ bI,
    const float* __restrict__ om,  const float* __restrict__ mb,
    float* __restrict__ out)
{
    const int b = blockIdx.x, t = threadIdx.x;
    const int w = t >> 5, l = t & 31;

    __shared__ float4 slotA[2][4];   // boundary b=w: post-A c0 of warp w+1 lane0
    __shared__ float4 slotU[2][4];   // boundary b=w: u of warp w lane31

    // thread t owns channels 8t .. 8t+7
    float cr[8], ci[8];
    {
        float4 r0 = ((const float4*)(stR + b * HH))[2 * t];
        float4 r1 = ((const float4*)(stR + b * HH))[2 * t + 1];
        float4 i0 = ((const float4*)(stI + b * HH))[2 * t];
        float4 i1 = ((const float4*)(stI + b * HH))[2 * t + 1];
        cr[0]=r0.x; cr[1]=r0.y; cr[2]=r0.z; cr[3]=r0.w;
        cr[4]=r1.x; cr[5]=r1.y; cr[6]=r1.z; cr[7]=r1.w;
        ci[0]=i0.x; ci[1]=i0.y; ci[2]=i0.z; ci[3]=i0.w;
        ci[4]=i1.x; ci[5]=i1.y; ci[6]=i1.z; ci[7]=i1.w;
    }

    const uint32_t baseA = (uint32_t)__cvta_generic_to_shared(slotA);
    const uint32_t baseU = (uint32_t)__cvta_generic_to_shared(slotU);
    const uint32_t sPubA = (uint32_t)(((w > 0) ? (w - 1) : 0) * 16);
    const uint32_t sPubU = (uint32_t)(w * 16);
    const uint32_t sRdA  = (uint32_t)(((w < 3) ? w : 2) * 16);
    const uint32_t sRdU  = (uint32_t)(((w > 0) ? (w - 1) : 0) * 16);
    const int isL0 = (l == 0), isL31 = (l == 31), isT0 = (t == 0);
    const int pubA = isL0 && (w > 0);
    const int pubU = isL31 && (w < 3);

    // coalesced trig streams: g_tA[k][j][t], layer stride 512 float4, j stride NT
    const float4* pA = &g_tA[0][0][t];
    const float4* pB = &g_tB[0][0][t];

    float4 tA[4], tB[4], nA[4], nB[4];
    #pragma unroll
    for (int j = 0; j < 4; j++) {
        tA[j] = ldg_v4_pinned(pA + j * NT);
        tB[j] = ldg_v4_pinned(pB + j * NT);
        nA[j] = ldg_v4_pinned(pA + 512 + j * NT);
        nB[j] = ldg_v4_pinned(pB + 512 + j * NT);
    }

    #pragma unroll 2
    for (int k = 0; k < LP; k++) {
        const uint32_t boff = (uint32_t)((k & 1) << 6);   // parity * 4 slots * 16B

        float4 cA[4], cB[4];
        #pragma unroll
        for (int j = 0; j < 4; j++) { cA[j] = tA[j]; cB[j] = tB[j]; }
        #pragma unroll
        for (int j = 0; j < 4; j++) { tA[j] = nA[j]; tB[j] = nB[j]; }
        const int off = (k + 2) * 512;
        #pragma unroll
        for (int j = 0; j < 4; j++) {
            nA[j] = ldg_v4_pinned(pA + off + j * NT);
            nB[j] = ldg_v4_pinned(pB + off + j * NT);
        }

        // ---- layer A: 4 independent MZIs (c2j, c2j+1) ----
        #pragma unroll
        for (int j = 0; j < 4; j++) {
            float pr = cA[j].x*cr[2*j] - cA[j].y*ci[2*j];
            float pi = cA[j].y*cr[2*j] + cA[j].x*ci[2*j];
            float n0r = cA[j].z*pr        - cA[j].w*ci[2*j+1];
            float n0i = cA[j].z*pi        + cA[j].w*cr[2*j+1];
            float n1r = cA[j].z*cr[2*j+1] - cA[j].w*pi;
            float n1i = cA[j].z*ci[2*j+1] + cA[j].w*pr;
            cr[2*j] = n0r; ci[2*j] = n0i; cr[2*j+1] = n1r; ci[2*j+1] = n1i;
        }
        // early publish: lane0's post-A c0 crosses the left boundary
        pub_pred(baseA + boff + sPubA, pubA, cr[0], ci[0], 0.f);

        // ---- edge B MZI (c7, next thread's c0): phase + u, publish right ----
        float p7r = cB[3].x*cr[7] - cB[3].y*ci[7];
        float p7i = cB[3].y*cr[7] + cB[3].x*ci[7];
        float u7x = cB[3].w*p7r, u7y = cB[3].w*p7i, u7z = cB[3].z;
        pub_pred(baseU + boff + sPubU, pubU, u7x, u7y, u7z);

        // intra-warp exchange
        float naXs = __shfl_down_sync(FULLMASK, cr[0], 1);
        float naYs = __shfl_down_sync(FULLMASK, ci[0], 1);
        float uxs  = __shfl_up_sync(FULLMASK, u7x, 1);
        float uys  = __shfl_up_sync(FULLMASK, u7y, 1);
        float uzs  = __shfl_up_sync(FULLMASK, u7z, 1);

        // ---- 3 mid B MZIs (c1,c2),(c3,c4),(c5,c6): thread-local, fill latency ----
        #pragma unroll
        for (int j = 0; j < 3; j++) {
            float pmr = cB[j].x*cr[2*j+1] - cB[j].y*ci[2*j+1];
            float pmi = cB[j].y*cr[2*j+1] + cB[j].x*ci[2*j+1];
            float n1r = cB[j].z*pmr        - cB[j].w*ci[2*j+2];
            float n1i = cB[j].z*pmi        + cB[j].w*cr[2*j+2];
            float n2r = cB[j].z*cr[2*j+2]  - cB[j].w*pmi;
            float n2i = cB[j].z*ci[2*j+2]  + cB[j].w*pmr;
            cr[2*j+1] = n1r; ci[2*j+1] = n1i; cr[2*j+2] = n2r; ci[2*j+2] = n2i;
        }

        __syncthreads();   // single CTA barrier per layer pair (4 warps)

        float4 sA = lds4(baseA + boff + sRdA);
        float4 sU = lds4(baseU + boff + sRdU);

        float naX = isL31 ? sA.x : naXs;   // t=127: cB[3] identity -> garbage harmless
        float naY = isL31 ? sA.y : naYs;
        float ux  = isL0 ? sU.x : uxs;
        float uy  = isL0 ? sU.y : uys;
        float uz  = isL0 ? sU.z : uzs;
        ux = isT0 ? 0.f : ux;              // t=0: channel 0 passes through
        uy = isT0 ? 0.f : uy;
        uz = isT0 ? 1.f : uz;

        // c7' = a-output of edge MZI; c0' = b-output of left edge MZI
        float n7r = cB[3].z*p7r - cB[3].w*naY;
        float n7i = cB[3].z*p7i + cB[3].w*naX;
        float n0r = uz*cr[0] - uy;
        float n0i = uz*ci[0] + ux;
        cr[7] = n7r; ci[7] = n7i; cr[0] = n0r; ci[0] = n0i;
    }

    // ---- epilogue (8 channels per thread) ----
    float ihR[8], ihI[8];
    {
        float4 r0 = ((const float4*)bR)[2 * t];
        float4 r1 = ((const float4*)bR)[2 * t + 1];
        float4 i0 = ((const float4*)bI)[2 * t];
        float4 i1 = ((const float4*)bI)[2 * t + 1];
        ihR[0]=r0.x; ihR[1]=r0.y; ihR[2]=r0.z; ihR[3]=r0.w;
        ihR[4]=r1.x; ihR[5]=r1.y; ihR[6]=r1.z; ihR[7]=r1.w;
        ihI[0]=i0.x; ihI[1]=i0.y; ihI[2]=i0.z; ihI[3]=i0.w;
        ihI[4]=i1.x; ihI[5]=i1.y; ihI[6]=i1.z; ihI[7]=i1.w;
    }
    #pragma unroll
    for (int c = 0; c < 4; c++) {
        #pragma unroll
        for (int h = 0; h < 2; h++) {
            float4 pr4 = *(const float4*)&g_pR[c][b * HH + 8 * t + 4 * h];
            float4 pi4 = *(const float4*)&g_pI[c][b * HH + 8 * t + 4 * h];
            ihR[4*h+0] += pr4.x; ihR[4*h+1] += pr4.y;
            ihR[4*h+2] += pr4.z; ihR[4*h+3] += pr4.w;
            ihI[4*h+0] += pi4.x; ihI[4*h+1] += pi4.y;
            ihI[4*h+2] += pi4.z; ihI[4*h+3] += pi4.w;
        }
    }
    float oma[8], mba[8];
    {
        float4 o0 = ((const float4*)om)[2 * t];
        float4 o1 = ((const float4*)om)[2 * t + 1];
        float4 m0 = ((const float4*)mb)[2 * t];
        float4 m1 = ((const float4*)mb)[2 * t + 1];
        oma[0]=o0.x; oma[1]=o0.y; oma[2]=o0.z; oma[3]=o0.w;
        oma[4]=o1.x; oma[5]=o1.y; oma[6]=o1.z; oma[7]=o1.w;
        mba[0]=m0.x; mba[1]=m0.y; mba[2]=m0.z; mba[3]=m0.w;
        mba[4]=m1.x; mba[5]=m1.y; mba[6]=m1.z; mba[7]=m1.w;
    }

    float zr[8], zi[8];
    #pragma unroll
    for (int j = 0; j < 8; j++) {
        float co, so;
        sincosf(oma[j], &so, &co);
        float zrr = ihR[j] + co*cr[j] - so*ci[j];
        float zii = ihI[j] + so*cr[j] + co*ci[j];
        float mag = sqrtf(zrr*zrr + zii*zii);
        float sc  = fmaxf(mag + mba[j], 0.f) / fmaxf(mag, 1e-8f);
        zr[j] = sc*zrr; zi[j] = sc*zii;
    }
    ((float4*)(out + b * HH))[2*t]               = make_float4(zr[0], zr[1], zr[2], zr[3]);
    ((float4*)(out + b * HH))[2*t + 1]           = make_float4(zr[4], zr[5], zr[6], zr[7]);
    ((float4*)(out + BB * HH + b * HH))[2*t]     = make_float4(zi[0], zi[1], zi[2], zi[3]);
    ((float4*)(out + BB * HH + b * HH))[2*t + 1] = make_float4(zi[4], zi[5], zi[6], zi[7]);
}

// ---------------------------------------------------------------------------
extern "C" void kernel_launch(void* const* d_in, const int* in_sizes, int n_in,
                              void* d_out, int out_size)
{
    const float* inR = (const float*)d_in[0];
    const float* inI = (const float*)d_in[1];
    const float* stR = (const float*)d_in[2];
    const float* stI = (const float*)d_in[3];
    const float* wR  = (const float*)d_in[4];
    const float* wI  = (const float*)d_in[5];
    const float* bR  = (const float*)d_in[6];
    const float* bI  = (const float*)d_in[7];
    const float* A0  = (const float*)d_in[8];
    const float* A1  = (const float*)d_in[9];
    const float* B0  = (const float*)d_in[10];
    const float* B1  = (const float*)d_in[11];
    const float* om  = (const float*)d_in[12];
    const float* mb  = (const float*)d_in[13];
    float* out = (float*)d_out;

    k1<<<256, 256>>>(inR, inI, wR, wI, A0, A1, B0, B1);
    k2<<<128, NT>>>(stR, stI, bR, bI, om, mb, out);
}